// round 17
// baseline (speedup 1.0000x reference)
#include <cuda_runtime.h>
#include <cstdint>

#define TH 1.0f
#define EPS_BN 1e-5f

// scratch (no allocations allowed -> device globals)
__device__ float g_dm[256 * 256];
__device__ int   g_rowok[256];
__device__ int   g_done  = 0;   // dm-row counter   (reset by group block)
__device__ int   g_ready = 0;   // gate: g_dm complete (reset by last worker)
__device__ int   g_wdone = 0;   // worker counter    (reset by last worker)

// ---------------------------------------------------------------------------
// Single fused kernel, 2304 blocks x 256 threads:
//  b in [0,256)    : dm blocks (wave 1). Thread m computes dm[b][m] -> g_dm,
//    rowok[b]. 256-count done-counter; last block computes group_indices
//    (fast path all-zeros; exact lax.scan replica fallback) and releases
//    g_ready.
//  b in [256,2304) : HOMOGENEOUS workers, no barriers. Phase 1: copy 32KB of
//    v -> v_grouped (overlaps dm). Phase 2: after g_ready, stream 16KB of
//    dist_mat_full (image t=i&127, rowgroup rg=i>>7) reading g_dm from hot
//    L2. 8 independent loads + 8 independent stores per thread.
// ---------------------------------------------------------------------------
__global__ void __launch_bounds__(256)
fused_kernel(const float* __restrict__ v,
             const float* __restrict__ w1,
             const float* __restrict__ b1,
             const float* __restrict__ bn_gamma,
             const float* __restrict__ bn_beta,
             const float* __restrict__ bn_mean,
             const float* __restrict__ bn_var,
             const float* __restrict__ w2,
             const float* __restrict__ b2,
             float* __restrict__ out) {
    int b = blockIdx.x;
    int tid = threadIdx.x;

    if (b >= 256) {
        int i = b - 256;                       // 0..2047
        // ---- phase 1: v_grouped = v_rel, 32KB slab ----
        const float4* __restrict__ v4 = (const float4*)v;
        float4* __restrict__ ov = (float4*)out;
        int i0 = i * 1024 + tid;
        float4 r0 = v4[i0];
        float4 r1 = v4[i0 + 256];
        float4 r2 = v4[i0 + 512];
        float4 r3 = v4[i0 + 768];
        ov[i0]       = r0;
        ov[i0 + 256] = r1;
        ov[i0 + 512] = r2;
        ov[i0 + 768] = r3;

        // ---- gate: wait for g_dm (normally already set) ----
        if (tid == 0) {
            while (atomicAdd(&g_ready, 0) == 0) __nanosleep(32);
        }
        __syncwarp();
        // all warps observe via the same path: cheap per-warp check
        if ((tid & 31) == 0 && tid != 0) {
            while (atomicAdd(&g_ready, 0) == 0) __nanosleep(32);
        }
        __syncwarp();
        __threadfence();                       // acquire g_dm writes

        // ---- phase 2: dist image t, rowgroup rg (16 rows = 16KB) ----
        int t  = i & 127;
        int rg = i >> 7;                       // 0..15
        const float4* __restrict__ dm4 = (const float4*)g_dm;
        float4* __restrict__ dd = (float4*)(out + 8388864);
        int sbase = rg * 1024 + tid;           // within g_dm (16384 float4)
        long dbase = (long)t * 16384 + sbase;  // within dist (2M float4)
        float4 s0 = dm4[sbase];
        float4 s1 = dm4[sbase + 256];
        float4 s2 = dm4[sbase + 512];
        float4 s3 = dm4[sbase + 768];
        dd[dbase]       = s0;
        dd[dbase + 256] = s1;
        dd[dbase + 512] = s2;
        dd[dbase + 768] = s3;

        // ---- replay-safe reset by the last worker ----
        if (tid == 0) {
            int old = atomicAdd(&g_wdone, 1);
            if (old == 2047) { g_wdone = 0; atomicExch(&g_ready, 0); }
        }
        return;
    }

    // ---- dm blocks ----
    __shared__ float sa[32], sw0[32], sw1[32], sb_[32];
    __shared__ float sK;
    __shared__ int s_islast;
    if (tid < 32) {
        float scale = bn_gamma[tid] * rsqrtf(bn_var[tid] + EPS_BN);
        float w2o = w2[tid];
        sa[tid]  = w2o * scale;
        sw0[tid] = w1[tid * 2 + 0];
        sw1[tid] = w1[tid * 2 + 1];
        sb_[tid] = b1[tid];
        float kpart = w2o * (bn_beta[tid] - bn_mean[tid] * scale);
        #pragma unroll
        for (int off = 16; off > 0; off >>= 1)
            kpart += __shfl_down_sync(0xffffffffu, kpart, off);
        if (tid == 0) sK = kpart + b2[0];
    }
    __syncthreads();

    int n = b;
    int m = tid;
    // x[c][i] = v_rel[0, c, 127, i], layout (1,256,128,256)
    const int base = 127 * 256;
    float d0 = v[base + n] - v[base + m];
    float d1 = v[32768 + base + n] - v[32768 + base + m];

    float sp = sK, sn = sK;
    #pragma unroll
    for (int o = 0; o < 32; o++) {
        float lin = sw0[o] * d0 + sw1[o] * d1;
        sp += sa[o] * fmaxf(lin + sb_[o], 0.0f);
        sn += sa[o] * fmaxf(sb_[o] - lin, 0.0f);
    }
    float val = 0.5f * (expf(sp) + expf(sn));
    g_dm[n * 256 + m] = val;

    int anyok = __syncthreads_or((m < n) && (val <= TH));
    if (tid == 0) {
        g_rowok[n] = anyok;
        __threadfence();                       // commit g_dm row + rowok
        int old = atomicAdd(&g_done, 1);
        s_islast = (old == 255);
    }
    __syncthreads();
    if (!s_islast) return;
    __threadfence();                           // see all rows' writes
    if (tid == 0) atomicExch(&g_ready, 1);     // release workers

    float* __restrict__ out_gi = out + 8388608;
    int rowok = g_rowok[tid];
    bool fast = __syncthreads_and(tid == 0 || rowok);
    if (fast) {
        // every row r>=1 merges into the component labeled 0 -> all ranks 0
        out_gi[tid] = 0.0f;
    } else {
        // ---- exact fallback: row-parallel replica of reference lax.scan ----
        __shared__ int comp[256];
        __shared__ int firstidx[256];
        __shared__ int marked[256];
        __shared__ int cstar;
        __shared__ int newcomp;
        comp[tid] = tid;
        __syncthreads();
        for (int r = 1; r < 256; r++) {
            firstidx[tid] = 0x7fffffff;
            marked[tid] = 0;
            if (tid == 0) cstar = -1;
            __syncthreads();
            int myc = comp[tid];
            int rcomp = comp[r];
            bool okc = (tid < r) && (g_dm[r * 256 + tid] <= TH);
            if (okc) { atomicMin(&firstidx[myc], tid); marked[myc] = 1; }
            if (tid == r) marked[myc] = 1;
            __syncthreads();
            if (okc && myc != rcomp && firstidx[myc] == tid)
                atomicMax(&cstar, tid);
            __syncthreads();
            int cs = cstar;
            if (cs >= 0 && tid == cs) newcomp = myc;
            __syncthreads();
            if (cs >= 0 && marked[myc]) comp[tid] = newcomp;
            __syncthreads();
        }
        __shared__ int pres[256];
        pres[tid] = 0;
        __syncthreads();
        pres[comp[tid]] = 1;
        __syncthreads();
        for (int off = 1; off < 256; off <<= 1) {
            int t = (tid >= off) ? pres[tid - off] : 0;
            __syncthreads();
            pres[tid] += t;
            __syncthreads();
        }
        out_gi[tid] = (float)(pres[comp[tid]] - 1);
    }
    __syncthreads();
    if (tid == 0) g_done = 0;                  // reset for next graph replay
}

extern "C" void kernel_launch(void* const* d_in, const int* in_sizes, int n_in,
                              void* d_out, int out_size) {
    const float* v_rel    = (const float*)d_in[0];
    const float* w1       = (const float*)d_in[1];
    const float* b1       = (const float*)d_in[2];
    const float* bn_gamma = (const float*)d_in[3];
    const float* bn_beta  = (const float*)d_in[4];
    const float* bn_mean  = (const float*)d_in[5];
    const float* bn_var   = (const float*)d_in[6];
    const float* w2       = (const float*)d_in[7];
    const float* b2       = (const float*)d_in[8];
    float* out = (float*)d_out;

    fused_kernel<<<2304, 256>>>(v_rel, w1, b1, bn_gamma, bn_beta, bn_mean,
                                bn_var, w2, b2, out);
}